// round 16
// baseline (speedup 1.0000x reference)
#include <cuda_runtime.h>
#include <cuda_fp16.h>
#include <math.h>
#include <stdint.h>

#define NB   8
#define CIN  128
#define CB   64
#define NPOS 4096
#define SH   72    // attn smem stride (halves)
#define STX  136   // proj X-transpose stride (halves): 128 cols + 8 pad
#define LOG2E 1.4426950408889634f
#define H2_ONES 0x3C003C00u   // fp16 {1.0, 1.0}

// fp16 operands, pre-converted by proj: [b][n][64] (hi/lo) ; vt: [b][d][n]
// g_qh/g_ql hold theta PRE-SCALED by log2(e) -> softmax uses exp2.
__device__ __align__(16) __half g_qh[NB * NPOS * CB];
__device__ __align__(16) __half g_ql[NB * NPOS * CB];
__device__ __align__(16) __half g_kh[NB * NPOS * CB];
__device__ __align__(16) __half g_kl[NB * NPOS * CB];
__device__ __align__(16) __half g_vt[NB * CB * NPOS];

// ---- helpers ---------------------------------------------------------------
__device__ __forceinline__ float ex2(float x) {
    float y;
    asm("ex2.approx.ftz.f32 %0, %1;" : "=f"(y) : "f"(x));
    return y;
}
__device__ __forceinline__ uint32_t ex2h2(uint32_t x) {
    uint32_t y;
    asm("ex2.approx.f16x2 %0, %1;" : "=r"(y) : "r"(x));
    return y;
}
__device__ __forceinline__ void cpasync16(uint32_t saddr, const void* g) {
    asm volatile("cp.async.ca.shared.global [%0], [%1], 16;"
                 :: "r"(saddr), "l"(g) : "memory");
}
#define CP_COMMIT() asm volatile("cp.async.commit_group;" ::: "memory")
#define CP_WAIT0()  asm volatile("cp.async.wait_group 0;" ::: "memory")

#define MMA16816(C, A0, A1, A2, A3, B0, B1)                                   \
    asm volatile("mma.sync.aligned.m16n8k16.row.col.f32.f16.f16.f32 "         \
                 "{%0,%1,%2,%3}, {%4,%5,%6,%7}, {%8,%9}, {%0,%1,%2,%3};"      \
                 : "+f"(C[0]), "+f"(C[1]), "+f"(C[2]), "+f"(C[3])             \
                 : "r"(A0), "r"(A1), "r"(A2), "r"(A3), "r"(B0), "r"(B1))

#define LDSM4(R0, R1, R2, R3, ADDR)                                           \
    asm volatile("ldmatrix.sync.aligned.m8n8.x4.shared.b16 {%0,%1,%2,%3}, [%4];" \
                 : "=r"(R0), "=r"(R1), "=r"(R2), "=r"(R3) : "r"(ADDR))

__device__ __forceinline__ uint32_t pack_h2(float a, float b) {
    __half2 h = __floats2half2_rn(a, b);
    return *(uint32_t*)&h;
}

// ---------------------------------------------------------------------------
// Kernel 1: proj via HMMA (3-term hi/lo split) — unchanged (passing, ~25us).
// ---------------------------------------------------------------------------
__global__ void __launch_bounds__(256) proj_kernel(
    const float* __restrict__ x, const float* __restrict__ wt,
    const float* __restrict__ wp, const float* __restrict__ wg)
{
    extern __shared__ __half hs[];
    __half* XH = hs;
    __half* XL = hs + 64 * STX;
    const int b   = blockIdx.y;
    const int n0  = blockIdx.x * 64;
    const int tid = threadIdx.x;
    const int w    = tid >> 5;
    const int lane = tid & 31;
    const int g8   = lane >> 2;
    const int qd   = lane & 3;

    const uint32_t sbase = (uint32_t)__cvta_generic_to_shared(hs);
    const uint32_t koffX = (uint32_t)((((lane & 7) + ((lane & 16) >> 1)) * STX + (lane & 8)) * 2);

    for (int i = tid; i < CIN * 64; i += 256) {
        int c = i >> 6, n = i & 63;
        float v = x[(b * CIN + c) * NPOS + n0 + n];
        __half h = __float2half_rn(v);
        XH[n * STX + c] = h;
        XL[n * STX + c] = __float2half_rn(v - __half2float(h));
    }
    __syncthreads();

    float acc[2][8][4];
    int tp[2], tmt[2], ntask = 0;

    for (int t = w; t < 12; t += 8) {
        int p  = t >> 2;
        int mt = t & 3;
        tp[ntask] = p; tmt[ntask] = mt;
        const float* W = (p == 0) ? wt : (p == 1) ? wp : wg;

#pragma unroll
        for (int nt = 0; nt < 8; nt++)
#pragma unroll
            for (int i = 0; i < 4; i++) acc[ntask][nt][i] = 0.f;

        const int r_lo = mt * 16 + g8;
        for (int ks = 0; ks < 8; ks++) {
            int cb = ks * 16 + 2 * qd;
            float2 w00 = *(const float2*)&W[r_lo * CIN + cb];
            float2 w10 = *(const float2*)&W[(r_lo + 8) * CIN + cb];
            float2 w02 = *(const float2*)&W[r_lo * CIN + cb + 8];
            float2 w12 = *(const float2*)&W[(r_lo + 8) * CIN + cb + 8];
            __half h00a = __float2half_rn(w00.x), h00b = __float2half_rn(w00.y);
            __half h10a = __float2half_rn(w10.x), h10b = __float2half_rn(w10.y);
            __half h02a = __float2half_rn(w02.x), h02b = __float2half_rn(w02.y);
            __half h12a = __float2half_rn(w12.x), h12b = __float2half_rn(w12.y);
            uint32_t a0 = pack_h2(__half2float(h00a), __half2float(h00b));
            uint32_t a1 = pack_h2(__half2float(h10a), __half2float(h10b));
            uint32_t a2 = pack_h2(__half2float(h02a), __half2float(h02b));
            uint32_t a3 = pack_h2(__half2float(h12a), __half2float(h12b));
            uint32_t e0 = pack_h2(w00.x - __half2float(h00a), w00.y - __half2float(h00b));
            uint32_t e1 = pack_h2(w10.x - __half2float(h10a), w10.y - __half2float(h10b));
            uint32_t e2 = pack_h2(w02.x - __half2float(h02a), w02.y - __half2float(h02b));
            uint32_t e3 = pack_h2(w12.x - __half2float(h12a), w12.y - __half2float(h12b));

#pragma unroll
            for (int ntp = 0; ntp < 4; ntp++) {
                uint32_t bh0, bh1, bh2, bh3, bl0, bl1, bl2, bl3;
                uint32_t ba = sbase + ((ntp * 16) * STX + ks * 16) * 2 + koffX;
                uint32_t bb = ba + (uint32_t)(64 * STX * 2);
                LDSM4(bh0, bh1, bh2, bh3, ba);
                LDSM4(bl0, bl1, bl2, bl3, bb);
                MMA16816(acc[ntask][2*ntp],   a0, a1, a2, a3, bh0, bh1);
                MMA16816(acc[ntask][2*ntp],   a0, a1, a2, a3, bl0, bl1);
                MMA16816(acc[ntask][2*ntp],   e0, e1, e2, e3, bh0, bh1);
                MMA16816(acc[ntask][2*ntp+1], a0, a1, a2, a3, bh2, bh3);
                MMA16816(acc[ntask][2*ntp+1], a0, a1, a2, a3, bl2, bl3);
                MMA16816(acc[ntask][2*ntp+1], e0, e1, e2, e3, bh2, bh3);
            }
        }
        ntask++;
    }
    __syncthreads();

    __half* QH2 = hs;
    __half* QL2 = hs + 64 * SH;
    __half* KH2 = hs + 2 * 64 * SH;
    __half* KL2 = hs + 3 * 64 * SH;
    __half* VT2 = hs + 4 * 64 * SH;

    for (int s = 0; s < ntask; s++) {
        int p = tp[s], mt = tmt[s];
        int k0r = mt * 16 + g8;
#pragma unroll
        for (int nt = 0; nt < 8; nt++) {
            int nn = nt * 8 + 2 * qd;
            float v0 = acc[s][nt][0], v1 = acc[s][nt][1];
            float v2 = acc[s][nt][2], v3 = acc[s][nt][3];
            if (p == 0) {
                v0 *= LOG2E; v1 *= LOG2E; v2 *= LOG2E; v3 *= LOG2E;
                __half h0 = __float2half_rn(v0), h1 = __float2half_rn(v1);
                __half h2 = __float2half_rn(v2), h3 = __float2half_rn(v3);
                QH2[nn * SH + k0r]           = h0;
                QH2[(nn + 1) * SH + k0r]     = h1;
                QH2[nn * SH + k0r + 8]       = h2;
                QH2[(nn + 1) * SH + k0r + 8] = h3;
                QL2[nn * SH + k0r]           = __float2half_rn(v0 - __half2float(h0));
                QL2[(nn + 1) * SH + k0r]     = __float2half_rn(v1 - __half2float(h1));
                QL2[nn * SH + k0r + 8]       = __float2half_rn(v2 - __half2float(h2));
                QL2[(nn + 1) * SH + k0r + 8] = __float2half_rn(v3 - __half2float(h3));
            } else if (p == 1) {
                __half h0 = __float2half_rn(v0), h1 = __float2half_rn(v1);
                __half h2 = __float2half_rn(v2), h3 = __float2half_rn(v3);
                KH2[nn * SH + k0r]           = h0;
                KH2[(nn + 1) * SH + k0r]     = h1;
                KH2[nn * SH + k0r + 8]       = h2;
                KH2[(nn + 1) * SH + k0r + 8] = h3;
                KL2[nn * SH + k0r]           = __float2half_rn(v0 - __half2float(h0));
                KL2[(nn + 1) * SH + k0r]     = __float2half_rn(v1 - __half2float(h1));
                KL2[nn * SH + k0r + 8]       = __float2half_rn(v2 - __half2float(h2));
                KL2[(nn + 1) * SH + k0r + 8] = __float2half_rn(v3 - __half2float(h3));
            } else {
                VT2[k0r * SH + nn]           = __float2half_rn(v0);
                VT2[k0r * SH + nn + 1]       = __float2half_rn(v1);
                VT2[(k0r + 8) * SH + nn]     = __float2half_rn(v2);
                VT2[(k0r + 8) * SH + nn + 1] = __float2half_rn(v3);
            }
        }
    }
    __syncthreads();

#pragma unroll
    for (int it = 0; it < 2; it++) {
        int ch = tid + it * 256;
        int r = ch >> 3, cc = ch & 7;
        size_t go = (size_t)(b * NPOS + n0 + r) * CB + cc * 8;
        *(uint4*)(g_qh + go) = *(const uint4*)(QH2 + r * SH + cc * 8);
        *(uint4*)(g_ql + go) = *(const uint4*)(QL2 + r * SH + cc * 8);
        *(uint4*)(g_kh + go) = *(const uint4*)(KH2 + r * SH + cc * 8);
        *(uint4*)(g_kl + go) = *(const uint4*)(KL2 + r * SH + cc * 8);
        *(uint4*)(g_vt + ((size_t)b * CB + r) * NPOS + n0 + cc * 8) =
            *(const uint4*)(VT2 + r * SH + cc * 8);
    }
}

// ---------------------------------------------------------------------------
// Kernel 2: flash attention + fused final projection & residual.
// Register-pressure fix: S+softmax computed PER 16-row tile (sc[8][4] live
// once), PV joint (V frags loaded once). K frags re-loaded per tile (cheap).
// ---------------------------------------------------------------------------
#define OQ_H  0
#define OQ_L  (128 * SH)
#define OKV   (2 * 128 * SH)
#define KVSZ  (3 * 64 * SH)
#define OK_L  (64 * SH)
#define OV_T  (2 * 64 * SH)
#define OW_L  (OKV + 128 * SH)

__global__ void __launch_bounds__(128, 2) attn_kernel(
    const float* __restrict__ wlast, const float* __restrict__ xg,
    float* __restrict__ outg)
{
    extern __shared__ __half hsm[];
    const int b   = blockIdx.y;
    const int n0  = blockIdx.x * 128;
    const int tid = threadIdx.x;
    const int w    = tid >> 5;
    const int lane = tid & 31;
    const int g8   = lane >> 2;
    const int qd   = lane & 3;

    const uint32_t sbase = (uint32_t)__cvta_generic_to_shared(hsm);
    const uint32_t qoff = (uint32_t)(((lane & 15) * SH + ((lane & 16) >> 1)) * 2);
    const uint32_t koff = (uint32_t)((((lane & 7) + ((lane & 16) >> 1)) * SH + (lane & 8)) * 2);

    const __half* khg_b = g_kh + (size_t)b * NPOS * CB;
    const __half* klg_b = g_kl + (size_t)b * NPOS * CB;
    const __half* vtg_b = g_vt + (size_t)b * CB * NPOS;

    const int r0 = tid >> 3;
    const int c0 = tid & 7;

    {
        uint32_t skv = sbase + OKV * 2;
#pragma unroll
        for (int i = 0; i < 4; i++) {
            int r = r0 + i * 16;
            cpasync16(skv + (r * SH + c0 * 8) * 2,        khg_b + r * CB + c0 * 8);
            cpasync16(skv + (OK_L + r * SH + c0 * 8) * 2, klg_b + r * CB + c0 * 8);
            cpasync16(skv + (OV_T + r * SH + c0 * 8) * 2, vtg_b + (size_t)r * NPOS + c0 * 8);
        }
    }
    CP_COMMIT();

    {
        const uint4* qh4 = (const uint4*)(g_qh + (size_t)(b * NPOS + n0) * CB);
        const uint4* ql4 = (const uint4*)(g_ql + (size_t)(b * NPOS + n0) * CB);
#pragma unroll
        for (int i = 0; i < 8; i++) {
            int ch = tid + i * 128;
            int r = ch >> 3, cc = ch & 7;
            *(uint4*)(hsm + OQ_H + r * SH + cc * 8) = qh4[r * 8 + cc];
            *(uint4*)(hsm + OQ_L + r * SH + cc * 8) = ql4[r * 8 + cc];
        }
    }

    float m01[2][2];
    float ls[2][4];
#pragma unroll
    for (int h = 0; h < 2; h++) {
        m01[h][0] = m01[h][1] = -INFINITY;
#pragma unroll
        for (int i = 0; i < 4; i++) ls[h][i] = 0.f;
    }
    float o[2][8][4];
#pragma unroll
    for (int h = 0; h < 2; h++)
#pragma unroll
        for (int dt = 0; dt < 8; dt++)
#pragma unroll
            for (int i = 0; i < 4; i++) o[h][dt][i] = 0.f;

    for (int kb = 0; kb < NPOS / 64; kb++) {
        const int p = kb & 1;
        CP_WAIT0();
        __syncthreads();

        if (kb + 1 < NPOS / 64) {
            const __half* khg = khg_b + (size_t)(kb + 1) * 64 * CB;
            const __half* klg = klg_b + (size_t)(kb + 1) * 64 * CB;
            const __half* vtg = vtg_b + (size_t)(kb + 1) * 64;
            uint32_t skv = sbase + (OKV + (p ^ 1) * KVSZ) * 2;
#pragma unroll
            for (int i = 0; i < 4; i++) {
                int r = r0 + i * 16;
                cpasync16(skv + (r * SH + c0 * 8) * 2,        khg + r * CB + c0 * 8);
                cpasync16(skv + (OK_L + r * SH + c0 * 8) * 2, klg + r * CB + c0 * 8);
                cpasync16(skv + (OV_T + r * SH + c0 * 8) * 2, vtg + (size_t)r * NPOS + c0 * 8);
            }
        }
        CP_COMMIT();

        const uint32_t sKh = sbase + (OKV + p * KVSZ) * 2;
        const uint32_t sKl = sKh + OK_L * 2;
        const uint32_t sVt = sKh + OV_T * 2;

        // ---- S + softmax, ONE 16-row tile at a time (register relief) ----
        uint32_t pa[2][4][4];
#pragma unroll
        for (int h = 0; h < 2; h++) {
            float sc[8][4];
#pragma unroll
            for (int nt = 0; nt < 8; nt++)
#pragma unroll
                for (int i = 0; i < 4; i++) sc[nt][i] = 0.f;

#pragma unroll
            for (int ks = 0; ks < 4; ks++) {
                uint32_t a0, a1, a2, a3, e0, e1, e2, e3;
                uint32_t qa = sbase + (OQ_H + (w * 32 + h * 16) * SH + ks * 16) * 2 + qoff;
                uint32_t la = sbase + (OQ_L + (w * 32 + h * 16) * SH + ks * 16) * 2 + qoff;
                LDSM4(a0, a1, a2, a3, qa);
                LDSM4(e0, e1, e2, e3, la);
#pragma unroll
                for (int ntp = 0; ntp < 4; ntp++) {
                    uint32_t kh0, kh1, kh2, kh3, kl0, kl1, kl2, kl3;
                    uint32_t ka = sKh + (ntp * 16 * SH + ks * 16) * 2 + koff;
                    uint32_t lb = sKl + (ntp * 16 * SH + ks * 16) * 2 + koff;
                    LDSM4(kh0, kh1, kh2, kh3, ka);
                    LDSM4(kl0, kl1, kl2, kl3, lb);
                    MMA16816(sc[2*ntp],   a0, a1, a2, a3, kh0, kh1);
                    MMA16816(sc[2*ntp],   a0, a1, a2, a3, kl0, kl1);
                    MMA16816(sc[2*ntp],   e0, e1, e2, e3, kh0, kh1);
                    MMA16816(sc[2*ntp+1], a0, a1, a2, a3, kh2, kh3);
                    MMA16816(sc[2*ntp+1], a0, a1, a2, a3, kl2, kl3);
                    MMA16816(sc[2*ntp+1], e0, e1, e2, e3, kh2, kh3);
                }
            }

            // online softmax (base 2, f16x2 exp); sc -> pa[h]
            float mx0 = -INFINITY, mx1 = -INFINITY;
#pragma unroll
            for (int nt = 0; nt < 8; nt++) {
                mx0 = fmaxf(mx0, fmaxf(sc[nt][0], sc[nt][1]));
                mx1 = fmaxf(mx1, fmaxf(sc[nt][2], sc[nt][3]));
            }
#pragma unroll
            for (int off = 1; off <= 2; off <<= 1) {
                mx0 = fmaxf(mx0, __shfl_xor_sync(0xffffffffu, mx0, off));
                mx1 = fmaxf(mx1, __shfl_xor_sync(0xffffffffu, mx1, off));
            }
            float mn0 = fmaxf(m01[h][0], mx0);
            float mn1 = fmaxf(m01[h][1], mx1);
            float s0 = ex2(m01[h][0] - mn0);
            float s1 = ex2(m01[h][1] - mn1);
            m01[h][0] = mn0;  m01[h][1] = mn1;

#pragma unroll
            for (int kc = 0; kc < 4; kc++) {
                pa[h][kc][0] = ex2h2(pack_h2(sc[2*kc][0]   - mn0, sc[2*kc][1]   - mn0));
                pa[h][kc][1] = ex2h2(pack_h2(sc[2*kc][2]   - mn1, sc[2*kc][3]   - mn1));
                pa[h][kc][2] = ex2h2(pack_h2(sc[2*kc+1][0] - mn0, sc[2*kc+1][1] - mn0));
                pa[h][kc][3] = ex2h2(pack_h2(sc[2*kc+1][2] - mn1, sc[2*kc+1][3] - mn1));
            }
#pragma unroll
            for (int dt = 0; dt < 8; dt++) {
                o[h][dt][0] *= s0; o[h][dt][1] *= s0;
                o[h][dt][2] *= s1; o[h][dt][3] *= s1;
            }
            ls[h][0] *= s0; ls[h][1] *= s0;
            ls[h][2] *= s1; ls[h][3] *= s1;
        }

        // ---- O += P V (joint; V frags loaded once) + row-sum MMAs ----
#pragma unroll
        for (int kc = 0; kc < 4; kc++) {
#pragma unroll
            for (int dtp = 0; dtp < 4; dtp++) {
                uint32_t v0, v1, v2, v3;
                uint32_t va = sVt + (dtp * 16 * SH + kc * 16) * 2 + koff;
                LDSM4(v0, v1, v2, v3, va);
#pragma unroll
                for (int h = 0; h < 2; h++) {
                    MMA16816(o[h][2*dtp],   pa[h][kc][0], pa[h][kc][1], pa[h][kc][2], pa[h][kc][3], v0, v1);
                    MMA16816(o[h][2*dtp+1], pa[h][kc][0], pa[h][kc][1], pa[h][kc][2], pa[h][kc][3], v2, v3);
                }
            }
#pragma unroll
            for (int h = 0; h < 2; h++)
                MMA16816(ls[h], pa[h][kc][0], pa[h][kc][1], pa[h][kc][2], pa[h][kc][3],
                         H2_ONES, H2_ONES);
        }
    }

    // ===== fused epilogue: out = w_last @ y + x =====
    __syncthreads();

    {
        __half* ysh = hsm + OQ_H;
        __half* ysl = hsm + OQ_L;
#pragma unroll
        for (int h = 0; h < 2; h++) {
            float inv0 = 1.f / ls[h][0], inv1 = 1.f / ls[h][2];
            int r = w * 32 + h * 16 + g8;
#pragma unroll
            for (int dt = 0; dt < 8; dt++) {
                int d = dt * 8 + 2 * qd;
                float y0 = o[h][dt][0] * inv0, y1 = o[h][dt][1] * inv0;
                float y2 = o[h][dt][2] * inv1, y3 = o[h][dt][3] * inv1;
                __half a0 = __float2half_rn(y0), a1 = __float2half_rn(y1);
                __half a2 = __float2half_rn(y2), a3 = __float2half_rn(y3);
                ysh[r * SH + d]           = a0;
                ysh[r * SH + d + 1]       = a1;
                ysh[(r + 8) * SH + d]     = a2;
                ysh[(r + 8) * SH + d + 1] = a3;
                ysl[r * SH + d]           = __float2half_rn(y0 - __half2float(a0));
                ysl[r * SH + d + 1]       = __float2half_rn(y1 - __half2float(a1));
                ysl[(r + 8) * SH + d]     = __float2half_rn(y2 - __half2float(a2));
                ysl[(r + 8) * SH + d + 1] = __float2half_rn(y3 - __half2float(a3));
            }
        }
    }
    {
        __half* wsh = hsm + OKV;
        __half* wsl = hsm + OW_L;
        const float4* wr = (const float4*)(wlast + tid * CB);
#pragma unroll
        for (int k4 = 0; k4 < 16; k4++) {
            float4 wv = wr[k4];
            float vv[4] = {wv.x, wv.y, wv.z, wv.w};
#pragma unroll
            for (int j = 0; j < 4; j++) {
                __half hh = __float2half_rn(vv[j]);
                wsh[tid * SH + k4 * 4 + j] = hh;
                wsl[tid * SH + k4 * 4 + j] = __float2half_rn(vv[j] - __half2float(hh));
            }
        }
    }
    __syncthreads();

#pragma unroll
    for (int nc = 0; nc < 4; nc++) {
        float acc[2][4][4];
#pragma unroll
        for (int ct = 0; ct < 2; ct++)
#pragma unroll
            for (int nt = 0; nt < 4; nt++)
#pragma unroll
                for (int i = 0; i < 4; i++) acc[ct][nt][i] = 0.f;

#pragma unroll
        for (int ks = 0; ks < 4; ks++) {
            uint32_t ah[2][4], al[2][4];
#pragma unroll
            for (int ct = 0; ct < 2; ct++) {
                uint32_t wa = sbase + (OKV + (w * 32 + ct * 16) * SH + ks * 16) * 2 + qoff;
                uint32_t wb = sbase + (OW_L + (w * 32 + ct * 16) * SH + ks * 16) * 2 + qoff;
                LDSM4(ah[ct][0], ah[ct][1], ah[ct][2], ah[ct][3], wa);
                LDSM4(al[ct][0], al[ct][1], al[ct][2], al[ct][3], wb);
            }
#pragma unroll
            for (int ntp = 0; ntp < 2; ntp++) {
                uint32_t bh0, bh1, bh2, bh3, bl0, bl1, bl2, bl3;
                uint32_t ba = sbase + (OQ_H + (nc * 32 + ntp * 16) * SH + ks * 16) * 2 + koff;
                uint32_t bb = sbase + (OQ_L + (nc * 32 + ntp * 16) * SH + ks * 16) * 2 + koff;
                LDSM4(bh0, bh1, bh2, bh3, ba);
                LDSM4(bl0, bl1, bl2, bl3, bb);
#pragma unroll
                for (int ct = 0; ct < 2; ct++) {
                    MMA16816(acc[ct][2*ntp],   ah[ct][0], ah[ct][1], ah[ct][2], ah[ct][3], bh0, bh1);
                    MMA16816(acc[ct][2*ntp],   ah[ct][0], ah[ct][1], ah[ct][2], ah[ct][3], bl0, bl1);
                    MMA16816(acc[ct][2*ntp],   al[ct][0], al[ct][1], al[ct][2], al[ct][3], bh0, bh1);
                    MMA16816(acc[ct][2*ntp+1], ah[ct][0], ah[ct][1], ah[ct][2], ah[ct][3], bh2, bh3);
                    MMA16816(acc[ct][2*ntp+1], ah[ct][0], ah[ct][1], ah[ct][2], ah[ct][3], bl2, bl3);
                    MMA16816(acc[ct][2*ntp+1], al[ct][0], al[ct][1], al[ct][2], al[ct][3], bh2, bh3);
                }
            }
        }

#pragma unroll
        for (int ct = 0; ct < 2; ct++) {
            int cr = w * 32 + ct * 16 + g8;
#pragma unroll
            for (int nt = 0; nt < 4; nt++) {
                int n = n0 + nc * 32 + nt * 8 + 2 * qd;
                size_t o0 = ((size_t)b * CIN + cr) * NPOS + n;
                size_t o1 = ((size_t)b * CIN + cr + 8) * NPOS + n;
                float2 x0 = *(const float2*)&xg[o0];
                float2 x1 = *(const float2*)&xg[o1];
                *(float2*)&outg[o0] =
                    make_float2(acc[ct][nt][0] + x0.x, acc[ct][nt][1] + x0.y);
                *(float2*)&outg[o1] =
                    make_float2(acc[ct][nt][2] + x1.x, acc[ct][nt][3] + x1.y);
            }
        }
    }
}

// ---------------------------------------------------------------------------
extern "C" void kernel_launch(void* const* d_in, const int* in_sizes, int n_in,
                              void* d_out, int out_size)
{
    const float* x  = (const float*)d_in[0];
    const float* wt = (const float*)d_in[1];
    const float* wp = (const float*)d_in[2];
    const float* wg = (const float*)d_in[3];
    const float* wl = (const float*)d_in[4];
    float* out = (float*)d_out;

    int smemX  = 2 * 64 * STX * (int)sizeof(__half);               // 34,816 B
    int smemEp = 5 * 64 * SH  * (int)sizeof(__half);               // 46,080 B
    int smem1  = (smemX > smemEp) ? smemX : smemEp;                // 46,080 B
    int smem2  = (2 * 128 * SH + 2 * KVSZ) * (int)sizeof(__half);  // 92,160 B
    cudaFuncSetAttribute(proj_kernel, cudaFuncAttributeMaxDynamicSharedMemorySize, smem1);
    cudaFuncSetAttribute(attn_kernel, cudaFuncAttributeMaxDynamicSharedMemorySize, smem2);

    dim3 grid1(NPOS / 64, NB);
    dim3 grid2(NPOS / 128, NB);
    proj_kernel<<<grid1, 256, smem1>>>(x, wt, wp, wg);
    attn_kernel<<<grid2, 128, smem2>>>(wl, x, out);
}

// round 17
// speedup vs baseline: 1.7355x; 1.7355x over previous
#include <cuda_runtime.h>
#include <cuda_fp16.h>
#include <math.h>
#include <stdint.h>

#define NB   8
#define CIN  128
#define CB   64
#define NPOS 4096
#define SH   72    // attn smem stride (halves)
#define STX  136   // proj X-transpose stride (halves): 128 cols + 8 pad
#define LOG2E 1.4426950408889634f
#define H2_ONES 0x3C003C00u   // fp16 {1.0, 1.0}

// fp16 operands, pre-converted by proj: [b][n][64] (hi/lo) ; vt: [b][d][n]
// g_qh/g_ql hold theta PRE-SCALED by log2(e) -> softmax uses exp2.
__device__ __align__(16) __half g_qh[NB * NPOS * CB];
__device__ __align__(16) __half g_ql[NB * NPOS * CB];
__device__ __align__(16) __half g_kh[NB * NPOS * CB];
__device__ __align__(16) __half g_kl[NB * NPOS * CB];
__device__ __align__(16) __half g_vt[NB * CB * NPOS];

// ---- helpers ---------------------------------------------------------------
__device__ __forceinline__ float ex2(float x) {
    float y;
    asm("ex2.approx.ftz.f32 %0, %1;" : "=f"(y) : "f"(x));
    return y;
}
__device__ __forceinline__ uint32_t ex2h2(uint32_t x) {
    uint32_t y;
    asm("ex2.approx.f16x2 %0, %1;" : "=r"(y) : "r"(x));
    return y;
}
__device__ __forceinline__ void cpasync16(uint32_t saddr, const void* g) {
    asm volatile("cp.async.ca.shared.global [%0], [%1], 16;"
                 :: "r"(saddr), "l"(g) : "memory");
}
#define CP_COMMIT() asm volatile("cp.async.commit_group;" ::: "memory")
#define CP_WAIT0()  asm volatile("cp.async.wait_group 0;" ::: "memory")

#define MMA16816(C, A0, A1, A2, A3, B0, B1)                                   \
    asm volatile("mma.sync.aligned.m16n8k16.row.col.f32.f16.f16.f32 "         \
                 "{%0,%1,%2,%3}, {%4,%5,%6,%7}, {%8,%9}, {%0,%1,%2,%3};"      \
                 : "+f"(C[0]), "+f"(C[1]), "+f"(C[2]), "+f"(C[3])             \
                 : "r"(A0), "r"(A1), "r"(A2), "r"(A3), "r"(B0), "r"(B1))

#define LDSM4(R0, R1, R2, R3, ADDR)                                           \
    asm volatile("ldmatrix.sync.aligned.m8n8.x4.shared.b16 {%0,%1,%2,%3}, [%4];" \
                 : "=r"(R0), "=r"(R1), "=r"(R2), "=r"(R3) : "r"(ADDR))

__device__ __forceinline__ uint32_t pack_h2(float a, float b) {
    __half2 h = __floats2half2_rn(a, b);
    return *(uint32_t*)&h;
}

// ---------------------------------------------------------------------------
// Kernel 1: proj via HMMA (3-term hi/lo split) — unchanged (passing, ~25us).
// ---------------------------------------------------------------------------
__global__ void __launch_bounds__(256) proj_kernel(
    const float* __restrict__ x, const float* __restrict__ wt,
    const float* __restrict__ wp, const float* __restrict__ wg)
{
    extern __shared__ __half hs[];
    __half* XH = hs;
    __half* XL = hs + 64 * STX;
    const int b   = blockIdx.y;
    const int n0  = blockIdx.x * 64;
    const int tid = threadIdx.x;
    const int w    = tid >> 5;
    const int lane = tid & 31;
    const int g8   = lane >> 2;
    const int qd   = lane & 3;

    const uint32_t sbase = (uint32_t)__cvta_generic_to_shared(hs);
    const uint32_t koffX = (uint32_t)((((lane & 7) + ((lane & 16) >> 1)) * STX + (lane & 8)) * 2);

    for (int i = tid; i < CIN * 64; i += 256) {
        int c = i >> 6, n = i & 63;
        float v = x[(b * CIN + c) * NPOS + n0 + n];
        __half h = __float2half_rn(v);
        XH[n * STX + c] = h;
        XL[n * STX + c] = __float2half_rn(v - __half2float(h));
    }
    __syncthreads();

    float acc[2][8][4];
    int tp[2], tmt[2], ntask = 0;

    for (int t = w; t < 12; t += 8) {
        int p  = t >> 2;
        int mt = t & 3;
        tp[ntask] = p; tmt[ntask] = mt;
        const float* W = (p == 0) ? wt : (p == 1) ? wp : wg;

#pragma unroll
        for (int nt = 0; nt < 8; nt++)
#pragma unroll
            for (int i = 0; i < 4; i++) acc[ntask][nt][i] = 0.f;

        const int r_lo = mt * 16 + g8;
        for (int ks = 0; ks < 8; ks++) {
            int cb = ks * 16 + 2 * qd;
            float2 w00 = *(const float2*)&W[r_lo * CIN + cb];
            float2 w10 = *(const float2*)&W[(r_lo + 8) * CIN + cb];
            float2 w02 = *(const float2*)&W[r_lo * CIN + cb + 8];
            float2 w12 = *(const float2*)&W[(r_lo + 8) * CIN + cb + 8];
            __half h00a = __float2half_rn(w00.x), h00b = __float2half_rn(w00.y);
            __half h10a = __float2half_rn(w10.x), h10b = __float2half_rn(w10.y);
            __half h02a = __float2half_rn(w02.x), h02b = __float2half_rn(w02.y);
            __half h12a = __float2half_rn(w12.x), h12b = __float2half_rn(w12.y);
            uint32_t a0 = pack_h2(__half2float(h00a), __half2float(h00b));
            uint32_t a1 = pack_h2(__half2float(h10a), __half2float(h10b));
            uint32_t a2 = pack_h2(__half2float(h02a), __half2float(h02b));
            uint32_t a3 = pack_h2(__half2float(h12a), __half2float(h12b));
            uint32_t e0 = pack_h2(w00.x - __half2float(h00a), w00.y - __half2float(h00b));
            uint32_t e1 = pack_h2(w10.x - __half2float(h10a), w10.y - __half2float(h10b));
            uint32_t e2 = pack_h2(w02.x - __half2float(h02a), w02.y - __half2float(h02b));
            uint32_t e3 = pack_h2(w12.x - __half2float(h12a), w12.y - __half2float(h12b));

#pragma unroll
            for (int ntp = 0; ntp < 4; ntp++) {
                uint32_t bh0, bh1, bh2, bh3, bl0, bl1, bl2, bl3;
                uint32_t ba = sbase + ((ntp * 16) * STX + ks * 16) * 2 + koffX;
                uint32_t bb = ba + (uint32_t)(64 * STX * 2);
                LDSM4(bh0, bh1, bh2, bh3, ba);
                LDSM4(bl0, bl1, bl2, bl3, bb);
                MMA16816(acc[ntask][2*ntp],   a0, a1, a2, a3, bh0, bh1);
                MMA16816(acc[ntask][2*ntp],   a0, a1, a2, a3, bl0, bl1);
                MMA16816(acc[ntask][2*ntp],   e0, e1, e2, e3, bh0, bh1);
                MMA16816(acc[ntask][2*ntp+1], a0, a1, a2, a3, bh2, bh3);
                MMA16816(acc[ntask][2*ntp+1], a0, a1, a2, a3, bl2, bl3);
                MMA16816(acc[ntask][2*ntp+1], e0, e1, e2, e3, bh2, bh3);
            }
        }
        ntask++;
    }
    __syncthreads();

    __half* QH2 = hs;
    __half* QL2 = hs + 64 * SH;
    __half* KH2 = hs + 2 * 64 * SH;
    __half* KL2 = hs + 3 * 64 * SH;
    __half* VT2 = hs + 4 * 64 * SH;

    for (int s = 0; s < ntask; s++) {
        int p = tp[s], mt = tmt[s];
        int k0r = mt * 16 + g8;
#pragma unroll
        for (int nt = 0; nt < 8; nt++) {
            int nn = nt * 8 + 2 * qd;
            float v0 = acc[s][nt][0], v1 = acc[s][nt][1];
            float v2 = acc[s][nt][2], v3 = acc[s][nt][3];
            if (p == 0) {
                v0 *= LOG2E; v1 *= LOG2E; v2 *= LOG2E; v3 *= LOG2E;
                __half h0 = __float2half_rn(v0), h1 = __float2half_rn(v1);
                __half h2 = __float2half_rn(v2), h3 = __float2half_rn(v3);
                QH2[nn * SH + k0r]           = h0;
                QH2[(nn + 1) * SH + k0r]     = h1;
                QH2[nn * SH + k0r + 8]       = h2;
                QH2[(nn + 1) * SH + k0r + 8] = h3;
                QL2[nn * SH + k0r]           = __float2half_rn(v0 - __half2float(h0));
                QL2[(nn + 1) * SH + k0r]     = __float2half_rn(v1 - __half2float(h1));
                QL2[nn * SH + k0r + 8]       = __float2half_rn(v2 - __half2float(h2));
                QL2[(nn + 1) * SH + k0r + 8] = __float2half_rn(v3 - __half2float(h3));
            } else if (p == 1) {
                __half h0 = __float2half_rn(v0), h1 = __float2half_rn(v1);
                __half h2 = __float2half_rn(v2), h3 = __float2half_rn(v3);
                KH2[nn * SH + k0r]           = h0;
                KH2[(nn + 1) * SH + k0r]     = h1;
                KH2[nn * SH + k0r + 8]       = h2;
                KH2[(nn + 1) * SH + k0r + 8] = h3;
                KL2[nn * SH + k0r]           = __float2half_rn(v0 - __half2float(h0));
                KL2[(nn + 1) * SH + k0r]     = __float2half_rn(v1 - __half2float(h1));
                KL2[nn * SH + k0r + 8]       = __float2half_rn(v2 - __half2float(h2));
                KL2[(nn + 1) * SH + k0r + 8] = __float2half_rn(v3 - __half2float(h3));
            } else {
                VT2[k0r * SH + nn]           = __float2half_rn(v0);
                VT2[k0r * SH + nn + 1]       = __float2half_rn(v1);
                VT2[(k0r + 8) * SH + nn]     = __float2half_rn(v2);
                VT2[(k0r + 8) * SH + nn + 1] = __float2half_rn(v3);
            }
        }
    }
    __syncthreads();

#pragma unroll
    for (int it = 0; it < 2; it++) {
        int ch = tid + it * 256;
        int r = ch >> 3, cc = ch & 7;
        size_t go = (size_t)(b * NPOS + n0 + r) * CB + cc * 8;
        *(uint4*)(g_qh + go) = *(const uint4*)(QH2 + r * SH + cc * 8);
        *(uint4*)(g_ql + go) = *(const uint4*)(QL2 + r * SH + cc * 8);
        *(uint4*)(g_kh + go) = *(const uint4*)(KH2 + r * SH + cc * 8);
        *(uint4*)(g_kl + go) = *(const uint4*)(KL2 + r * SH + cc * 8);
        *(uint4*)(g_vt + ((size_t)b * CB + r) * NPOS + n0 + cc * 8) =
            *(const uint4*)(VT2 + r * SH + cc * 8);
    }
}

// ---------------------------------------------------------------------------
// Kernel 2: flash attention + fused final projection & residual.
// R15 structure (joint-tile S, f16x2 exp, ones-MMA row sums) + warp-uniform
// rescale-skip (numerically identical: skipped path is exact multiply-by-1).
// ---------------------------------------------------------------------------
#define OQ_H  0
#define OQ_L  (128 * SH)
#define OKV   (2 * 128 * SH)
#define KVSZ  (3 * 64 * SH)
#define OK_L  (64 * SH)
#define OV_T  (2 * 64 * SH)
#define OW_L  (OKV + 128 * SH)

__global__ void __launch_bounds__(128, 2) attn_kernel(
    const float* __restrict__ wlast, const float* __restrict__ xg,
    float* __restrict__ outg)
{
    extern __shared__ __half hsm[];
    const int b   = blockIdx.y;
    const int n0  = blockIdx.x * 128;
    const int tid = threadIdx.x;
    const int w    = tid >> 5;
    const int lane = tid & 31;
    const int g8   = lane >> 2;
    const int qd   = lane & 3;

    const uint32_t sbase = (uint32_t)__cvta_generic_to_shared(hsm);
    const uint32_t qoff = (uint32_t)(((lane & 15) * SH + ((lane & 16) >> 1)) * 2);
    const uint32_t koff = (uint32_t)((((lane & 7) + ((lane & 16) >> 1)) * SH + (lane & 8)) * 2);

    const __half* khg_b = g_kh + (size_t)b * NPOS * CB;
    const __half* klg_b = g_kl + (size_t)b * NPOS * CB;
    const __half* vtg_b = g_vt + (size_t)b * CB * NPOS;

    const int r0 = tid >> 3;
    const int c0 = tid & 7;

    {
        uint32_t skv = sbase + OKV * 2;
#pragma unroll
        for (int i = 0; i < 4; i++) {
            int r = r0 + i * 16;
            cpasync16(skv + (r * SH + c0 * 8) * 2,        khg_b + r * CB + c0 * 8);
            cpasync16(skv + (OK_L + r * SH + c0 * 8) * 2, klg_b + r * CB + c0 * 8);
            cpasync16(skv + (OV_T + r * SH + c0 * 8) * 2, vtg_b + (size_t)r * NPOS + c0 * 8);
        }
    }
    CP_COMMIT();

    {
        const uint4* qh4 = (const uint4*)(g_qh + (size_t)(b * NPOS + n0) * CB);
        const uint4* ql4 = (const uint4*)(g_ql + (size_t)(b * NPOS + n0) * CB);
#pragma unroll
        for (int i = 0; i < 8; i++) {
            int ch = tid + i * 128;
            int r = ch >> 3, cc = ch & 7;
            *(uint4*)(hsm + OQ_H + r * SH + cc * 8) = qh4[r * 8 + cc];
            *(uint4*)(hsm + OQ_L + r * SH + cc * 8) = ql4[r * 8 + cc];
        }
    }

    float m01[2][2];
    float ls[2][4];
#pragma unroll
    for (int h = 0; h < 2; h++) {
        m01[h][0] = m01[h][1] = -INFINITY;
#pragma unroll
        for (int i = 0; i < 4; i++) ls[h][i] = 0.f;
    }
    float o[2][8][4];
#pragma unroll
    for (int h = 0; h < 2; h++)
#pragma unroll
        for (int dt = 0; dt < 8; dt++)
#pragma unroll
            for (int i = 0; i < 4; i++) o[h][dt][i] = 0.f;

    for (int kb = 0; kb < NPOS / 64; kb++) {
        const int p = kb & 1;
        CP_WAIT0();
        __syncthreads();

        if (kb + 1 < NPOS / 64) {
            const __half* khg = khg_b + (size_t)(kb + 1) * 64 * CB;
            const __half* klg = klg_b + (size_t)(kb + 1) * 64 * CB;
            const __half* vtg = vtg_b + (size_t)(kb + 1) * 64;
            uint32_t skv = sbase + (OKV + (p ^ 1) * KVSZ) * 2;
#pragma unroll
            for (int i = 0; i < 4; i++) {
                int r = r0 + i * 16;
                cpasync16(skv + (r * SH + c0 * 8) * 2,        khg + r * CB + c0 * 8);
                cpasync16(skv + (OK_L + r * SH + c0 * 8) * 2, klg + r * CB + c0 * 8);
                cpasync16(skv + (OV_T + r * SH + c0 * 8) * 2, vtg + (size_t)r * NPOS + c0 * 8);
            }
        }
        CP_COMMIT();

        const uint32_t sKh = sbase + (OKV + p * KVSZ) * 2;
        const uint32_t sKl = sKh + OK_L * 2;
        const uint32_t sVt = sKh + OV_T * 2;

        // ---- S = Q K^T (both tiles jointly; LDSM frags; 12 indep chains) ----
        float sc[2][8][4];
#pragma unroll
        for (int h = 0; h < 2; h++)
#pragma unroll
            for (int nt = 0; nt < 8; nt++)
#pragma unroll
                for (int i = 0; i < 4; i++) sc[h][nt][i] = 0.f;

#pragma unroll
        for (int ks = 0; ks < 4; ks++) {
            uint32_t a[2][4], e[2][4];
#pragma unroll
            for (int h = 0; h < 2; h++) {
                uint32_t qa = sbase + (OQ_H + (w * 32 + h * 16) * SH + ks * 16) * 2 + qoff;
                uint32_t la = sbase + (OQ_L + (w * 32 + h * 16) * SH + ks * 16) * 2 + qoff;
                LDSM4(a[h][0], a[h][1], a[h][2], a[h][3], qa);
                LDSM4(e[h][0], e[h][1], e[h][2], e[h][3], la);
            }
#pragma unroll
            for (int ntp = 0; ntp < 4; ntp++) {
                uint32_t kh0, kh1, kh2, kh3, kl0, kl1, kl2, kl3;
                uint32_t ka = sKh + (ntp * 16 * SH + ks * 16) * 2 + koff;
                uint32_t lb = sKl + (ntp * 16 * SH + ks * 16) * 2 + koff;
                LDSM4(kh0, kh1, kh2, kh3, ka);
                LDSM4(kl0, kl1, kl2, kl3, lb);
#pragma unroll
                for (int h = 0; h < 2; h++) {
                    MMA16816(sc[h][2*ntp],   a[h][0], a[h][1], a[h][2], a[h][3], kh0, kh1);
                    MMA16816(sc[h][2*ntp],   a[h][0], a[h][1], a[h][2], a[h][3], kl0, kl1);
                    MMA16816(sc[h][2*ntp],   e[h][0], e[h][1], e[h][2], e[h][3], kh0, kh1);
                    MMA16816(sc[h][2*ntp+1], a[h][0], a[h][1], a[h][2], a[h][3], kh2, kh3);
                    MMA16816(sc[h][2*ntp+1], a[h][0], a[h][1], a[h][2], a[h][3], kl2, kl3);
                    MMA16816(sc[h][2*ntp+1], e[h][0], e[h][1], e[h][2], e[h][3], kh2, kh3);
                }
            }
        }

        // ---- online softmax (base 2, f16x2 exp); warp-uniform rescale skip ----
        uint32_t pa[2][4][4];
#pragma unroll
        for (int h = 0; h < 2; h++) {
            float mx0 = -INFINITY, mx1 = -INFINITY;
#pragma unroll
            for (int nt = 0; nt < 8; nt++) {
                mx0 = fmaxf(mx0, fmaxf(sc[h][nt][0], sc[h][nt][1]));
                mx1 = fmaxf(mx1, fmaxf(sc[h][nt][2], sc[h][nt][3]));
            }
#pragma unroll
            for (int off = 1; off <= 2; off <<= 1) {
                mx0 = fmaxf(mx0, __shfl_xor_sync(0xffffffffu, mx0, off));
                mx1 = fmaxf(mx1, __shfl_xor_sync(0xffffffffu, mx1, off));
            }
            float mn0 = m01[h][0], mn1 = m01[h][1];
            bool upd = !__all_sync(0xffffffffu, (mx0 <= mn0) & (mx1 <= mn1));
            if (upd) {
                mn0 = fmaxf(mn0, mx0);
                mn1 = fmaxf(mn1, mx1);
                float s0 = ex2(m01[h][0] - mn0);
                float s1 = ex2(m01[h][1] - mn1);
                m01[h][0] = mn0;  m01[h][1] = mn1;
#pragma unroll
                for (int dt = 0; dt < 8; dt++) {
                    o[h][dt][0] *= s0; o[h][dt][1] *= s0;
                    o[h][dt][2] *= s1; o[h][dt][3] *= s1;
                }
                ls[h][0] *= s0; ls[h][1] *= s0;
                ls[h][2] *= s1; ls[h][3] *= s1;
            }

#pragma unroll
            for (int kc = 0; kc < 4; kc++) {
                pa[h][kc][0] = ex2h2(pack_h2(sc[h][2*kc][0]   - mn0, sc[h][2*kc][1]   - mn0));
                pa[h][kc][1] = ex2h2(pack_h2(sc[h][2*kc][2]   - mn1, sc[h][2*kc][3]   - mn1));
                pa[h][kc][2] = ex2h2(pack_h2(sc[h][2*kc+1][0] - mn0, sc[h][2*kc+1][1] - mn0));
                pa[h][kc][3] = ex2h2(pack_h2(sc[h][2*kc+1][2] - mn1, sc[h][2*kc+1][3] - mn1));
            }
        }

        // ---- O += P V (V frags loaded once, both tiles) + row-sum MMAs ----
#pragma unroll
        for (int kc = 0; kc < 4; kc++) {
#pragma unroll
            for (int dtp = 0; dtp < 4; dtp++) {
                uint32_t v0, v1, v2, v3;
                uint32_t va = sVt + (dtp * 16 * SH + kc * 16) * 2 + koff;
                LDSM4(v0, v1, v2, v3, va);
#pragma unroll
                for (int h = 0; h < 2; h++) {
                    MMA16816(o[h][2*dtp],   pa[h][kc][0], pa[h][kc][1], pa[h][kc][2], pa[h][kc][3], v0, v1);
                    MMA16816(o[h][2*dtp+1], pa[h][kc][0], pa[h][kc][1], pa[h][kc][2], pa[h][kc][3], v2, v3);
                }
            }
#pragma unroll
            for (int h = 0; h < 2; h++)
                MMA16816(ls[h], pa[h][kc][0], pa[h][kc][1], pa[h][kc][2], pa[h][kc][3],
                         H2_ONES, H2_ONES);
        }
    }

    // ===== fused epilogue: out = w_last @ y + x =====
    __syncthreads();

    {
        __half* ysh = hsm + OQ_H;
        __half* ysl = hsm + OQ_L;
#pragma unroll
        for (int h = 0; h < 2; h++) {
            float inv0 = 1.f / ls[h][0], inv1 = 1.f / ls[h][2];
            int r = w * 32 + h * 16 + g8;
#pragma unroll
            for (int dt = 0; dt < 8; dt++) {
                int d = dt * 8 + 2 * qd;
                float y0 = o[h][dt][0] * inv0, y1 = o[h][dt][1] * inv0;
                float y2 = o[h][dt][2] * inv1, y3 = o[h][dt][3] * inv1;
                __half a0 = __float2half_rn(y0), a1 = __float2half_rn(y1);
                __half a2 = __float2half_rn(y2), a3 = __float2half_rn(y3);
                ysh[r * SH + d]           = a0;
                ysh[r * SH + d + 1]       = a1;
                ysh[(r + 8) * SH + d]     = a2;
                ysh[(r + 8) * SH + d + 1] = a3;
                ysl[r * SH + d]           = __float2half_rn(y0 - __half2float(a0));
                ysl[r * SH + d + 1]       = __float2half_rn(y1 - __half2float(a1));
                ysl[(r + 8) * SH + d]     = __float2half_rn(y2 - __half2float(a2));
                ysl[(r + 8) * SH + d + 1] = __float2half_rn(y3 - __half2float(a3));
            }
        }
    }
    {
        __half* wsh = hsm + OKV;
        __half* wsl = hsm + OW_L;
        const float4* wr = (const float4*)(wlast + tid * CB);
#pragma unroll
        for (int k4 = 0; k4 < 16; k4++) {
            float4 wv = wr[k4];
            float vv[4] = {wv.x, wv.y, wv.z, wv.w};
#pragma unroll
            for (int j = 0; j < 4; j++) {
                __half hh = __float2half_rn(vv[j]);
                wsh[tid * SH + k4 * 4 + j] = hh;
                wsl[tid * SH + k4 * 4 + j] = __float2half_rn(vv[j] - __half2float(hh));
            }
        }
    }
    __syncthreads();

#pragma unroll
    for (int nc = 0; nc < 4; nc++) {
        float acc[2][4][4];
#pragma unroll
        for (int ct = 0; ct < 2; ct++)
#pragma unroll
            for (int nt = 0; nt < 4; nt++)
#pragma unroll
                for (int i = 0; i < 4; i++) acc[ct][nt][i] = 0.f;

#pragma unroll
        for (int ks = 0; ks < 4; ks++) {
            uint32_t ah[2][4], al[2][4];
#pragma unroll
            for (int ct = 0; ct < 2; ct++) {
                uint32_t wa = sbase + (OKV + (w * 32 + ct * 16) * SH + ks * 16) * 2 + qoff;
                uint32_t wb = sbase + (OW_L + (w * 32 + ct * 16) * SH + ks * 16) * 2 + qoff;
                LDSM4(ah[ct][0], ah[ct][1], ah[ct][2], ah[ct][3], wa);
                LDSM4(al[ct][0], al[ct][1], al[ct][2], al[ct][3], wb);
            }
#pragma unroll
            for (int ntp = 0; ntp < 2; ntp++) {
                uint32_t bh0, bh1, bh2, bh3, bl0, bl1, bl2, bl3;
                uint32_t ba = sbase + (OQ_H + (nc * 32 + ntp * 16) * SH + ks * 16) * 2 + koff;
                uint32_t bb = sbase + (OQ_L + (nc * 32 + ntp * 16) * SH + ks * 16) * 2 + koff;
                LDSM4(bh0, bh1, bh2, bh3, ba);
                LDSM4(bl0, bl1, bl2, bl3, bb);
#pragma unroll
                for (int ct = 0; ct < 2; ct++) {
                    MMA16816(acc[ct][2*ntp],   ah[ct][0], ah[ct][1], ah[ct][2], ah[ct][3], bh0, bh1);
                    MMA16816(acc[ct][2*ntp],   ah[ct][0], ah[ct][1], ah[ct][2], ah[ct][3], bl0, bl1);
                    MMA16816(acc[ct][2*ntp],   al[ct][0], al[ct][1], al[ct][2], al[ct][3], bh0, bh1);
                    MMA16816(acc[ct][2*ntp+1], ah[ct][0], ah[ct][1], ah[ct][2], ah[ct][3], bh2, bh3);
                    MMA16816(acc[ct][2*ntp+1], ah[ct][0], ah[ct][1], ah[ct][2], ah[ct][3], bl2, bl3);
                    MMA16816(acc[ct][2*ntp+1], al[ct][0], al[ct][1], al[ct][2], al[ct][3], bh2, bh3);
                }
            }
        }

#pragma unroll
        for (int ct = 0; ct < 2; ct++) {
            int cr = w * 32 + ct * 16 + g8;
#pragma unroll
            for (int nt = 0; nt < 4; nt++) {
                int n = n0 + nc * 32 + nt * 8 + 2 * qd;
                size_t o0 = ((size_t)b * CIN + cr) * NPOS + n;
                size_t o1 = ((size_t)b * CIN + cr + 8) * NPOS + n;
                float2 x0 = *(const float2*)&xg[o0];
                float2 x1 = *(const float2*)&xg[o1];
                *(float2*)&outg[o0] =
                    make_float2(acc[ct][nt][0] + x0.x, acc[ct][nt][1] + x0.y);
                *(float2*)&outg[o1] =
                    make_float2(acc[ct][nt][2] + x1.x, acc[ct][nt][3] + x1.y);
            }
        }
    }
}

// ---------------------------------------------------------------------------
extern "C" void kernel_launch(void* const* d_in, const int* in_sizes, int n_in,
                              void* d_out, int out_size)
{
    const float* x  = (const float*)d_in[0];
    const float* wt = (const float*)d_in[1];
    const float* wp = (const float*)d_in[2];
    const float* wg = (const float*)d_in[3];
    const float* wl = (const float*)d_in[4];
    float* out = (float*)d_out;

    int smemX  = 2 * 64 * STX * (int)sizeof(__half);               // 34,816 B
    int smemEp = 5 * 64 * SH  * (int)sizeof(__half);               // 46,080 B
    int smem1  = (smemX > smemEp) ? smemX : smemEp;                // 46,080 B
    int smem2  = (2 * 128 * SH + 2 * KVSZ) * (int)sizeof(__half);  // 92,160 B
    cudaFuncSetAttribute(proj_kernel, cudaFuncAttributeMaxDynamicSharedMemorySize, smem1);
    cudaFuncSetAttribute(attn_kernel, cudaFuncAttributeMaxDynamicSharedMemorySize, smem2);

    dim3 grid1(NPOS / 64, NB);
    dim3 grid2(NPOS / 128, NB);
    proj_kernel<<<grid1, 256, smem1>>>(x, wt, wp, wg);
    attn_kernel<<<grid2, 128, smem2>>>(wl, x, out);
}